// round 11
// baseline (speedup 1.0000x reference)
#include <cuda_runtime.h>
#include <cstdint>

// NMS_20933670600803  — heatmap (B,1,14,14) f32 -> [m1 | m2] f32
//
// R11: TWO items per warp for ILP. Each item's NMS chain
// (tree -> REDUX -> table LDG -> suppress) is serial; two independent items
// interleaved in one warp overlap those latencies (REDUX ~30cyc, L1 ~39cyc).
//
// Keys (validated R4-R10, rel_err 0):
//   key = (max(fb, bits(0.6f)) << 8) + (0xE66666FF - i)  [mod 2^32]
// below-threshold / suppressed -> key = 255 - i; unsigned max == jnp.argmax
// (max value, tie -> smallest index). Warp reduce = REDUX.MAX.U32.
// Dead slots (i >= 196) load 0.0 -> key = 255-i <= 59 < 60 <= live keys.
//
// Suppression: 200KB global table of final AND operands (0x000000FF inside
// window, 0xFFFFFFFF outside); one coalesced LDG.128 pair + 8 LOPs per item
// per iteration.

#define NPIX 196
#define NVEC 49
#define WPB  8
#define THREADS (WPB * 32)
#define KTHR   0x3F19999Au      // __float_as_uint(0.6f)
#define MUL14  306790400u       // 18725 << 14 ; umulhi(i, MUL14) = i/14 (i<256)

struct alignas(16) AndTable {
    unsigned w[196][2][32][4];
    constexpr AndTable() : w{} {
        for (int bi = 0; bi < 196; ++bi) {
            const int x = bi / 14, y = bi % 14;
            const int x1 = (x - 5 > 0) ? x - 5 : 0;
            const int x2 = (x + 5 < 15) ? x + 5 : 15;
            const int y1 = (y - 5 > 0) ? y - 5 : 0;
            const int y2 = (y + 5 < 15) ? y + 5 : 15;
            for (int half = 0; half < 2; ++half)
                for (int lane = 0; lane < 32; ++lane)
                    for (int c = 0; c < 4; ++c) {
                        const int i = half * 128 + 4 * lane + c;
                        unsigned op = 0xFFFFFFFFu;
                        if (i < 196) {
                            const int eu = i / 14, ev = i % 14;
                            if (eu >= x1 && eu < x2 && ev >= y1 && ev < y2)
                                op = 0x000000FFu;
                        }
                        w[bi][half][lane][c] = op;
                    }
        }
    }
};
__device__ const AndTable g_tbl;     // ~200KB global, constexpr-initialized

__global__ __launch_bounds__(THREADS)
void nms_masks_kernel(const float4* __restrict__ hm,
                      float4* __restrict__ out,
                      int B)
{
    const int warp = blockIdx.x * WPB + (threadIdx.x >> 5);
    const int lane = threadIdx.x & 31;
    const int item0 = 2 * warp;                    // this warp's two items
    if (item0 + 1 >= B + 1) return;                // grid sized exactly; keep guard cheap

    const int i0 = 4 * lane;
    const int i1 = 128 + 4 * lane;
    const bool has2 = (lane < 17);

    // ---- front-loaded loads for both items (MLP up to 6) ----
    const float4* __restrict__ p0 = hm + (size_t)item0 * NVEC;
    const float4* __restrict__ p1 = p0 + NVEC;

    float4 va[2], vb[2];
    va[0] = __ldcs(p0 + lane);
    va[1] = __ldcs(p1 + lane);
    vb[0] = make_float4(0.f, 0.f, 0.f, 0.f);
    vb[1] = make_float4(0.f, 0.f, 0.f, 0.f);
    if (has2) {
        vb[0] = __ldcs(p0 + lane + 32);
        vb[1] = __ldcs(p1 + lane + 32);
    }

    unsigned key[2][8];
#pragma unroll
    for (int j = 0; j < 2; ++j) {
        const float vals[8] = {va[j].x, va[j].y, va[j].z, va[j].w,
                               vb[j].x, vb[j].y, vb[j].z, vb[j].w};
#pragma unroll
        for (int c = 0; c < 8; ++c) {
            const int i = (c < 4) ? (i0 + c) : (i1 + c - 4);
            const unsigned fb = __float_as_uint(vals[c]);
            const unsigned M  = (fb > KTHR) ? fb : KTHR;          // IMNMX.U32
            key[j][c] = M * 256u + (0xE66666FFu - (unsigned)i);   // IMAD
        }
    }

    int bis[2][4];
#pragma unroll
    for (int it = 0; it < 4; ++it) {
        // interleaved trees (independent -> ILP)
        unsigned m[2];
#pragma unroll
        for (int j = 0; j < 2; ++j)
            m[j] = max(max(max(key[j][0], key[j][1]), max(key[j][2], key[j][3])),
                       max(max(key[j][4], key[j][5]), max(key[j][6], key[j][7])));

        // two REDUXes back-to-back (latency overlapped)
        const unsigned w0 = __reduce_max_sync(0xffffffffu, m[0]);
        const unsigned w1 = __reduce_max_sync(0xffffffffu, m[1]);
        const int bi0 = (int)((~w0) & 0xFFu);
        const int bi1 = (int)((~w1) & 0xFFu);
        bis[0][it] = bi0;
        bis[1][it] = bi1;

        if (it < 3) {
            // 4 coalesced LDG.128, MLP=4, table L1/L2-resident
            const uint4 a0 = __ldg(reinterpret_cast<const uint4*>(g_tbl.w[bi0][0][lane]));
            const uint4 b0 = __ldg(reinterpret_cast<const uint4*>(g_tbl.w[bi0][1][lane]));
            const uint4 a1 = __ldg(reinterpret_cast<const uint4*>(g_tbl.w[bi1][0][lane]));
            const uint4 b1 = __ldg(reinterpret_cast<const uint4*>(g_tbl.w[bi1][1][lane]));
            key[0][0] &= a0.x; key[0][1] &= a0.y; key[0][2] &= a0.z; key[0][3] &= a0.w;
            key[0][4] &= b0.x; key[0][5] &= b0.y; key[0][6] &= b0.z; key[0][7] &= b0.w;
            key[1][0] &= a1.x; key[1][1] &= a1.y; key[1][2] &= a1.z; key[1][3] &= a1.w;
            key[1][4] &= b1.x; key[1][5] &= b1.y; key[1][6] &= b1.z; key[1][7] &= b1.w;
        }
    }

    // ---- per-item uniform tail + emission ----
#pragma unroll
    for (int j = 0; j < 2; ++j) {
        int px[4], py[4], pk[4];
#pragma unroll
        for (int t = 0; t < 4; ++t) {
            const int x = (int)__umulhi((unsigned)bis[j][t], MUL14);   // bi / 14
            const int y = bis[j][t] - 14 * x;
            px[t] = x; py[t] = y; pk[t] = x | (y << 4);
        }

        unsigned kbest = 0;
        {
            const int pa[6] = {0, 0, 0, 1, 1, 2};
            const int pb[6] = {1, 2, 3, 2, 3, 3};
#pragma unroll
            for (int q = 0; q < 6; ++q) {
                const int dx = px[pb[q]] - px[pa[q]];
                const int dy = py[pb[q]] - py[pa[q]];
                const int d  = dx * dx + dy * dy;       // <= 338
                const unsigned kd = ((unsigned)d << 20) | ((unsigned)(5 - q) << 16)
                                  | (unsigned)(pk[pa[q]] | (pk[pb[q]] << 8));
                kbest = (kbest > kd) ? kbest : kd;
            }
        }
        const int ax = (int)(kbest & 0xFu);
        const int ay = (int)((kbest >> 4)  & 0xFu);
        const int bx = (int)((kbest >> 8)  & 0xFu);
        const int by = (int)((kbest >> 12) & 0xFu);

        // d1 - d2 = Cy*i + Cg*eu + mCc
        const int dxc = bx - ax, dyc = by - ay;
        const int Cy  = 2 * dyc;
        const int Cg  = 2 * dxc - 14 * Cy;
        const int mCc = -(dxc * (ax + bx) + dyc * (ay + by));

        float4* __restrict__ o1 = out + (size_t)(item0 + j) * NVEC;
        float4* __restrict__ o2 = o1 + (size_t)B * NVEC;

        {
            float r1[4], r2[4];
#pragma unroll
            for (int c = 0; c < 4; ++c) {
                const int i  = i0 + c;
                const int eu = (int)__umulhi((unsigned)i, MUL14);
                const int pv = Cy * i + (Cg * eu + mCc);
                const unsigned m1b = ((unsigned)pv >> 31) * 0x3F800000u;
                r1[c] = __uint_as_float(m1b);
                r2[c] = 1.0f - r1[c];
            }
            __stcs(o1 + lane, make_float4(r1[0], r1[1], r1[2], r1[3]));
            __stcs(o2 + lane, make_float4(r2[0], r2[1], r2[2], r2[3]));
        }
        if (has2) {
            float r1[4], r2[4];
#pragma unroll
            for (int c = 0; c < 4; ++c) {
                const int i  = i1 + c;
                const int eu = (int)__umulhi((unsigned)i, MUL14);
                const int pv = Cy * i + (Cg * eu + mCc);
                const unsigned m1b = ((unsigned)pv >> 31) * 0x3F800000u;
                r1[c] = __uint_as_float(m1b);
                r2[c] = 1.0f - r1[c];
            }
            __stcs(o1 + lane + 32, make_float4(r1[0], r1[1], r1[2], r1[3]));
            __stcs(o2 + lane + 32, make_float4(r2[0], r2[1], r2[2], r2[3]));
        }
    }
}

extern "C" void kernel_launch(void* const* d_in, const int* in_sizes, int n_in,
                              void* d_out, int out_size)
{
    const float4* hm  = (const float4*)d_in[0];
    float4*       out = (float4*)d_out;
    const int B = in_sizes[0] / NPIX;              // 131072
    const int nwarps = B / 2;                      // 2 items per warp
    const int grid = (nwarps + WPB - 1) / WPB;     // 8192
    nms_masks_kernel<<<grid, THREADS>>>(hm, out, B);
}

// round 12
// speedup vs baseline: 1.1182x; 1.1182x over previous
#include <cuda_runtime.h>
#include <cstdint>

// NMS_20933670600803  — heatmap (B,1,14,14) f32 -> [m1 | m2] f32
//
// R12: HALF-WARP items. Each 16-lane half owns one batch item, so one
// instruction stream (tree, REDUX, table load, suppress, decode, pair,
// emission) serves TWO items at ~1.6x the cost of one:
//  - __reduce_max_sync with split masks (0x0000FFFF / 0xFFFF0000) does both
//    items' argmax in ONE instruction.
//  - one table LDG.128/iter covers both items (each half reads its bi row).
//  - all post-loop scalar work is per-lane, i.e. shared across items.
//
// Keys (validated R4-R11, rel_err 0):
//   key = (max(fb, bits(0.6f)) << 8) + (0xE66666FF - i)  [mod 2^32]
//       = v>0.6 ? ((fb-KTHR)<<8 | (255-i)) : (255-i)
// unsigned max == jnp.argmax (max value, tie -> smallest index).
// Dead slots (i >= 196) collapse to 255-i <= 59 < 60 <= live keys.
//
// Lane q (= lane&15) of half h owns elements 4q+64s+c (s<3, c<4) and, for
// q<4, element 192+q. Suppression: per-(bi,q) uint4 byte-mask table (50KB,
// global, L1-resident): words x,y,z bytes c -> elems 4q+64s+c; word w byte0
// -> elem 192+q. Expand with PRMT, apply with one LOP3.

#define NPIX 196
#define NVEC 49
#define WPB  8
#define THREADS (WPB * 32)
#define KTHR   0x3F19999Au      // __float_as_uint(0.6f)
#define MUL14  306790400u       // 18725 << 14 ; umulhi(i, MUL14) = i/14 (i<256)

struct alignas(16) HalfTable {
    // w[bi][q] : uint4; bytes = 0xFF if element suppressed by peak bi else 0
    //   word0 byte c -> elem 4q+c ; word1 -> 64+4q+c ; word2 -> 128+4q+c
    //   word3 byte0  -> elem 192+q (only q<4 meaningful)
    unsigned w[196][16][4];
    constexpr HalfTable() : w{} {
        for (int bi = 0; bi < 196; ++bi) {
            const int x = bi / 14, y = bi % 14;
            const int x1 = (x - 5 > 0) ? x - 5 : 0;
            const int x2 = (x + 5 < 15) ? x + 5 : 15;
            const int y1 = (y - 5 > 0) ? y - 5 : 0;
            const int y2 = (y + 5 < 15) ? y + 5 : 15;
            for (int q = 0; q < 16; ++q) {
                for (int s = 0; s < 3; ++s) {
                    unsigned word = 0;
                    for (int c = 0; c < 4; ++c) {
                        const int i = 4 * q + 64 * s + c;
                        const int eu = i / 14, ev = i % 14;
                        if (eu >= x1 && eu < x2 && ev >= y1 && ev < y2)
                            word |= 0xFFu << (8 * c);
                    }
                    w[bi][q][s] = word;
                }
                unsigned w3 = 0;
                if (q < 4) {
                    const int i = 192 + q;
                    const int eu = i / 14, ev = i % 14;
                    if (eu >= x1 && eu < x2 && ev >= y1 && ev < y2)
                        w3 = 0xFFu;
                }
                w[bi][q][3] = w3;
            }
        }
    }
};
__device__ const HalfTable g_tbl;    // 50176 B global, constexpr-initialized

__global__ __launch_bounds__(THREADS)
void nms_masks_kernel(const float4* __restrict__ hm,
                      float4* __restrict__ out,
                      int B)
{
    const int warp = blockIdx.x * WPB + (threadIdx.x >> 5);
    const int lane = threadIdx.x & 31;
    const int q    = lane & 15;               // lane within half
    const int h    = lane >> 4;               // half index: 0 or 1
    const int item = 2 * warp + h;
    if (item >= B) return;

    const unsigned gmask = 0xFFFFu << (16 * h);   // this half's REDUX mask

    const float4* __restrict__ p = hm + (size_t)item * NVEC;
    const float4 f0 = __ldcs(p + q);              // elems 4q   .. 4q+3
    const float4 f1 = __ldcs(p + q + 16);         // elems 64+4q..
    const float4 f2 = __ldcs(p + q + 32);         // elems 128+4q..
    float e3 = 0.0f;                              // elem 192+q (q<4)
    if (q < 4) e3 = __ldcs(reinterpret_cast<const float*>(p) + 192 + q);

    // ---- keys ----
    unsigned key[13];
    {
        const float vals[12] = {f0.x, f0.y, f0.z, f0.w,
                                f1.x, f1.y, f1.z, f1.w,
                                f2.x, f2.y, f2.z, f2.w};
        const unsigned base = 0xE66666FFu - 4u * (unsigned)q;
#pragma unroll
        for (int c = 0; c < 12; ++c) {
            const unsigned fb = __float_as_uint(vals[c]);
            const unsigned M  = (fb > KTHR) ? fb : KTHR;              // IMNMX.U32
            key[c] = M * 256u + (base - (unsigned)(64 * (c >> 2) + (c & 3)));
        }
        // elem 192+q ; for q>=4 e3=0 -> key = 255-(192+q) <= 59, never wins
        const unsigned fb = __float_as_uint(e3);
        const unsigned M  = (fb > KTHR) ? fb : KTHR;
        key[12] = M * 256u + (0xE66666FFu - (unsigned)(192 + q));
    }

    int bis[4];
#pragma unroll
    for (int it = 0; it < 4; ++it) {
        // local max over 13 keys (12 IMNMX)
        unsigned m = max(key[0], key[1]);
        m = max(m, max(key[2],  key[3]));
        m = max(m, max(key[4],  key[5]));
        m = max(m, max(key[6],  key[7]));
        m = max(m, max(key[8],  key[9]));
        m = max(m, max(key[10], key[11]));
        m = max(m, key[12]);

        // one REDUX serves both halves (disjoint masks)
        const unsigned w = __reduce_max_sync(gmask, m);
        const int bi = (int)((~w) & 0xFFu);
        bis[it] = bi;

        if (it < 3) {
            const uint4 t = __ldg(reinterpret_cast<const uint4*>(g_tbl.w[bi][q]));
            const unsigned tw[3] = {t.x, t.y, t.z};
#pragma unroll
            for (int s = 0; s < 3; ++s)
#pragma unroll
                for (int c = 0; c < 4; ++c) {
                    const unsigned mm = __byte_perm(tw[s], 0u, 0x1111 * c);
                    key[4 * s + c] &= (~mm | 0xFFu);   // single LOP3
                }
            const unsigned m12 = __byte_perm(t.w, 0u, 0x0000);
            key[12] &= (~m12 | 0xFFu);
        }
    }

    // ---- per-half scalar tail (computed once per lane, covers its item) ----
    int px[4], py[4], pk[4];
#pragma unroll
    for (int t = 0; t < 4; ++t) {
        const int x = (int)__umulhi((unsigned)bis[t], MUL14);     // bi / 14
        const int y = bis[t] - 14 * x;
        px[t] = x; py[t] = y; pk[t] = x | (y << 4);
    }

    unsigned kbest = 0;
    {
        const int pa[6] = {0, 0, 0, 1, 1, 2};
        const int pb[6] = {1, 2, 3, 2, 3, 3};
#pragma unroll
        for (int qq = 0; qq < 6; ++qq) {
            const int dx = px[pb[qq]] - px[pa[qq]];
            const int dy = py[pb[qq]] - py[pa[qq]];
            const int d  = dx * dx + dy * dy;       // <= 338
            const unsigned kd = ((unsigned)d << 20) | ((unsigned)(5 - qq) << 16)
                              | (unsigned)(pk[pa[qq]] | (pk[pb[qq]] << 8));
            kbest = (kbest > kd) ? kbest : kd;
        }
    }
    const int ax = (int)(kbest & 0xFu);
    const int ay = (int)((kbest >> 4)  & 0xFu);
    const int bx = (int)((kbest >> 8)  & 0xFu);
    const int by = (int)((kbest >> 12) & 0xFu);

    // d1 - d2 = Cy*i + Cg*eu + mCc   (ev = i - 14*eu folded in)
    const int dxc = bx - ax, dyc = by - ay;
    const int Cy  = 2 * dyc;
    const int Cg  = 2 * dxc - 14 * Cy;
    const int mCc = -(dxc * (ax + bx) + dyc * (ay + by));

    float4* __restrict__ o1 = out + (size_t)item * NVEC;
    float4* __restrict__ o2 = o1 + (size_t)B * NVEC;

#pragma unroll
    for (int s = 0; s < 3; ++s) {
        float r1[4], r2[4];
#pragma unroll
        for (int c = 0; c < 4; ++c) {
            const int i  = 4 * q + 64 * s + c;
            const int eu = (int)__umulhi((unsigned)i, MUL14);        // i / 14
            const int pv = Cy * i + (Cg * eu + mCc);                 // 2x IMAD
            const unsigned m1b = ((unsigned)pv >> 31) * 0x3F800000u; // SHF + IMAD
            r1[c] = __uint_as_float(m1b);       // 1.0f if d1<d2 else 0.0f
            r2[c] = 1.0f - r1[c];               // FADD, exact on {0,1}
        }
        __stcs(o1 + q + 16 * s, make_float4(r1[0], r1[1], r1[2], r1[3]));
        __stcs(o2 + q + 16 * s, make_float4(r2[0], r2[1], r2[2], r2[3]));
    }
    if (q < 4) {                                 // elems 192..195, scalar
        const int i  = 192 + q;                  // eu = 13
        const int pv = Cy * i + (Cg * 13 + mCc);
        const unsigned m1b = ((unsigned)pv >> 31) * 0x3F800000u;
        const float r1 = __uint_as_float(m1b);
        __stcs(reinterpret_cast<float*>(o1) + i, r1);
        __stcs(reinterpret_cast<float*>(o2) + i, 1.0f - r1);
    }
}

extern "C" void kernel_launch(void* const* d_in, const int* in_sizes, int n_in,
                              void* d_out, int out_size)
{
    const float4* hm  = (const float4*)d_in[0];
    float4*       out = (float4*)d_out;
    const int B = in_sizes[0] / NPIX;              // 131072
    const int nwarps = (B + 1) / 2;                // 2 items per warp
    const int grid = (nwarps + WPB - 1) / WPB;     // 8192
    nms_masks_kernel<<<grid, THREADS>>>(hm, out, B);
}